// round 5
// baseline (speedup 1.0000x reference)
#include <cuda_runtime.h>
#include <cstdint>

// ---------------- problem constants ----------------
#define Hh  64
#define Ww  64
#define Cc  64
#define Uu  64
#define OHh 30
#define OWw 30
#define KDIM   1600           // 5*5*64
#define NCHUNK 50             // KDIM / 32
#define LDSS   36             // smem row stride in floats

__device__ __forceinline__ uint32_t cvt_tf32(float v) {
    uint32_t r;
    asm("cvt.rna.tf32.f32 %0, %1;" : "=r"(r) : "f"(v));
    return r;
}

__device__ __forceinline__ void mma_16n8k8(float c[4], const uint32_t a[4], const uint32_t b[2]) {
    asm volatile(
        "mma.sync.aligned.m16n8k8.row.col.f32.tf32.tf32.f32 "
        "{%0,%1,%2,%3}, {%4,%5,%6,%7}, {%8,%9}, {%0,%1,%2,%3};"
        : "+f"(c[0]), "+f"(c[1]), "+f"(c[2]), "+f"(c[3])
        : "r"(a[0]), "r"(a[1]), "r"(a[2]), "r"(a[3]), "r"(b[0]), "r"(b[1]));
}

__device__ __forceinline__ void cp16(uint32_t dst, const float* src) {
    asm volatile("cp.async.cg.shared.global [%0], [%1], 16;" :: "r"(dst), "l"(src));
}
// W is streaming / read-once: evict_first so it doesn't blow x out of L2.
__device__ __forceinline__ void cp16_ef(uint32_t dst, const float* src, uint64_t pol) {
    asm volatile("cp.async.cg.shared.global.L2::cache_hint [%0], [%1], 16, %2;"
                 :: "r"(dst), "l"(src), "l"(pol));
}
#define CP_COMMIT() asm volatile("cp.async.commit_group;" ::: "memory")

// ---------------- kernel ----------------
__global__ void __launch_bounds__(128, 6)
freeconv_mma_kernel(const float* __restrict__ x, const float* __restrict__ w,
                    const float* __restrict__ bias, float* __restrict__ out) {
    __shared__ float As[2][64][LDSS];
    __shared__ float Bs[2][64][LDSS];
    __shared__ float bsh[64];

    const int tid  = threadIdx.x;
    const int wid  = tid >> 5;
    const int lane = tid & 31;
    const int g    = lane >> 2;     // 0..7
    const int t    = lane & 3;      // 0..3
    const int tile = blockIdx.x;
    const int oh = tile / OWw, ow = tile % OWw;
    const int ih0 = oh * 2, iw0 = ow * 2;
    const int warpM = (wid >> 1) * 32;   // 0 or 32
    const int warpN = (wid & 1) * 32;    // 0 or 32

    uint64_t pol;
    asm("createpolicy.fractional.L2::evict_first.b64 %0, 1.0;" : "=l"(pol));

    if (tid < 64) bsh[tid] = bias[(size_t)tile * Uu + tid];

    const size_t wtile = (size_t)tile * Uu * KDIM;

    // per-thread constant staging coords
    const int srow = tid >> 1;              // 0..63 (2 threads per row)
    const int sc16 = (tid & 1) * 4;         // 16B chunk index base: 0 or 4
    // rows covered per iteration pair handled below via it loop (4 iters of 128 thr)

    // Stage one K-chunk (32 floats wide): A rows = 64 batches, B rows = 64 units.
    // xoff = word offset of x chunk base (incrementally maintained by caller).
    auto load_chunk = [&](size_t xoff, int chunk, int s) {
        const float* xsrc = x + xoff;
        const float* wsrc = w + wtile + (size_t)chunk * 32;
#pragma unroll
        for (int it = 0; it < 4; it++) {
            const int idx = tid + it * 128;      // 0..511
            const int row = idx >> 3, c16 = idx & 7;
            uint32_t ad = (uint32_t)__cvta_generic_to_shared(&As[s][row][0]) + c16 * 16;
            cp16(ad, xsrc + (size_t)row * (Hh * Ww * Cc) + c16 * 4);
            uint32_t bd = (uint32_t)__cvta_generic_to_shared(&Bs[s][row][0]) + c16 * 16;
            cp16_ef(bd, wsrc + (size_t)row * KDIM + c16 * 4, pol);
        }
    };

    float acc[2][4][4];
#pragma unroll
    for (int mt = 0; mt < 2; mt++)
#pragma unroll
        for (int nt = 0; nt < 4; nt++)
#pragma unroll
            for (int r = 0; r < 4; r++) acc[mt][nt][r] = 0.0f;

    // incremental (i, j, ch) tracking for the x chunk offset (uniform ints, no div)
    const size_t xrow0 = (((size_t)ih0 * Ww) + iw0) * Cc;   // (i=0, j=0)
    size_t xoff = xrow0;            // current chunk's x word offset
    int ji = 0, ii = 0, ch = 0;     // j, i, half-channel of current chunk

    // next-chunk offset stepper (call once per chunk consumed)
    auto step = [&]() {
        if (ch == 0) { ch = 1; xoff += 32; }
        else {
            ch = 0; xoff -= 32;
            if (ji < 4) { ji++; xoff += Cc; }
            else        { ji = 0; ii++; xoff += (size_t)Ww * Cc - 4 * Cc; }
        }
    };

    load_chunk(xoff, 0, 0);
    CP_COMMIT();

    for (int c = 0; c < NCHUNK; c++) {
        const int s = c & 1;
        if (c + 1 < NCHUNK) {
            step();
            load_chunk(xoff, c + 1, s ^ 1);
            CP_COMMIT();
            asm volatile("cp.async.wait_group 1;" ::: "memory");
        } else {
            asm volatile("cp.async.wait_group 0;" ::: "memory");
        }
        __syncthreads();

#pragma unroll
        for (int k8 = 0; k8 < 4; k8++) {
            const int kb = k8 * 8;
            const int co = kb + 2 * t;   // canonical k t -> col kb+2t, t+4 -> kb+2t+1
            uint32_t a[2][4], b[4][2];
#pragma unroll
            for (int mt = 0; mt < 2; mt++) {
                const int r0 = warpM + mt * 16 + g;
                float2 lo = *reinterpret_cast<const float2*>(&As[s][r0][co]);
                float2 hi = *reinterpret_cast<const float2*>(&As[s][r0 + 8][co]);
                a[mt][0] = cvt_tf32(lo.x);
                a[mt][2] = cvt_tf32(lo.y);
                a[mt][1] = cvt_tf32(hi.x);
                a[mt][3] = cvt_tf32(hi.y);
            }
#pragma unroll
            for (int nt = 0; nt < 4; nt++) {
                const int n0 = warpN + nt * 8 + g;
                float2 bv = *reinterpret_cast<const float2*>(&Bs[s][n0][co]);
                b[nt][0] = cvt_tf32(bv.x);
                b[nt][1] = cvt_tf32(bv.y);
            }
#pragma unroll
            for (int mt = 0; mt < 2; mt++)
#pragma unroll
                for (int nt = 0; nt < 4; nt++)
                    mma_16n8k8(acc[mt][nt], a[mt], b[nt]);
        }
        __syncthreads();
    }

    // epilogue: D[row=m, col=u] += bias[u]; out[b][oh][ow][u]
#pragma unroll
    for (int mt = 0; mt < 2; mt++) {
        const int r0 = warpM + mt * 16 + g;
#pragma unroll
        for (int nt = 0; nt < 4; nt++) {
            const int col = warpN + nt * 8 + 2 * t;
            const float b0 = bsh[col], b1 = bsh[col + 1];
            float* op0 = out + (((size_t)r0 * OHh + oh) * OWw + ow) * Uu + col;
            float* op1 = out + (((size_t)(r0 + 8) * OHh + oh) * OWw + ow) * Uu + col;
            float2 v0 = make_float2(acc[mt][nt][0] + b0, acc[mt][nt][1] + b1);
            float2 v1 = make_float2(acc[mt][nt][2] + b0, acc[mt][nt][3] + b1);
            *reinterpret_cast<float2*>(op0) = v0;
            *reinterpret_cast<float2*>(op1) = v1;
        }
    }
}

// ---------------- launch ----------------
extern "C" void kernel_launch(void* const* d_in, const int* in_sizes, int n_in,
                              void* d_out, int out_size) {
    (void)in_sizes; (void)n_in; (void)out_size;
    const float* x = (const float*)d_in[0];
    const float* w = (const float*)d_in[1];
    const float* b = (const float*)d_in[2];
    freeconv_mma_kernel<<<OHh * OWw, 128>>>(x, w, b, (float*)d_out);
}

// round 6
// speedup vs baseline: 1.2206x; 1.2206x over previous
#include <cuda_runtime.h>
#include <cstdint>

// ---------------- problem constants ----------------
#define Hh  64
#define Ww  64
#define Cc  64
#define Uu  64
#define OHh 30
#define OWw 30
#define KDIM   1600           // 5*5*64
#define NCHUNK 50             // KDIM / 32
#define LDSS   36             // smem row stride in floats (bank=(4g+t)%32 -> conflict-free)

// Raw fp32 bits into the tf32 mma: HW reads the tf32 lanes of the register,
// i.e. truncation-to-tf32. Saves 96 cvt instructions per warp-chunk.
__device__ __forceinline__ uint32_t tf32_bits(float v) { return __float_as_uint(v); }

__device__ __forceinline__ void mma_16n8k8(float c[4], const uint32_t a[4], const uint32_t b[2]) {
    asm volatile(
        "mma.sync.aligned.m16n8k8.row.col.f32.tf32.tf32.f32 "
        "{%0,%1,%2,%3}, {%4,%5,%6,%7}, {%8,%9}, {%0,%1,%2,%3};"
        : "+f"(c[0]), "+f"(c[1]), "+f"(c[2]), "+f"(c[3])
        : "r"(a[0]), "r"(a[1]), "r"(a[2]), "r"(a[3]), "r"(b[0]), "r"(b[1]));
}

__device__ __forceinline__ void cp16(uint32_t dst, const float* src) {
    asm volatile("cp.async.cg.shared.global [%0], [%1], 16;" :: "r"(dst), "l"(src));
}
// W is streaming / read-once: evict_first so it doesn't blow x out of L2.
__device__ __forceinline__ void cp16_ef(uint32_t dst, const float* src, uint64_t pol) {
    asm volatile("cp.async.cg.shared.global.L2::cache_hint [%0], [%1], 16, %2;"
                 :: "r"(dst), "l"(src), "l"(pol));
}
#define CP_COMMIT() asm volatile("cp.async.commit_group;" ::: "memory")

// ---------------- kernel ----------------
__global__ void __launch_bounds__(128, 6)
freeconv_mma_kernel(const float* __restrict__ x, const float* __restrict__ w,
                    const float* __restrict__ bias, float* __restrict__ out) {
    __shared__ float As[2][64][LDSS];
    __shared__ float Bs[2][64][LDSS];
    __shared__ float bsh[64];

    const int tid  = threadIdx.x;
    const int wid  = tid >> 5;
    const int lane = tid & 31;
    const int g    = lane >> 2;     // 0..7
    const int t    = lane & 3;      // 0..3
    const int tile = blockIdx.x;
    const int oh = tile / OWw, ow = tile % OWw;
    const int ih0 = oh * 2, iw0 = ow * 2;
    const int warpM = (wid >> 1) * 32;   // 0 or 32
    const int warpN = (wid & 1) * 32;    // 0 or 32

    uint64_t pol;
    asm("createpolicy.fractional.L2::evict_first.b64 %0, 1.0;" : "=l"(pol));

    if (tid < 64) bsh[tid] = bias[(size_t)tile * Uu + tid];

    const size_t wtile = (size_t)tile * Uu * KDIM;

    // Stage one K-chunk (32 floats wide): A rows = 64 batches, B rows = 64 units.
    auto load_chunk = [&](int chunk, int s) {
        const int ij = chunk >> 1, ch = chunk & 1;
        const int i = ij / 5, j = ij - i * 5;
        const float* xsrc = x + (((size_t)(ih0 + i) * Ww) + (iw0 + j)) * Cc + ch * 32;
        const float* wsrc = w + wtile + (size_t)chunk * 32;
#pragma unroll
        for (int it = 0; it < 4; it++) {
            const int idx = tid + it * 128;      // 0..511
            const int row = idx >> 3, c16 = idx & 7;
            uint32_t ad = (uint32_t)__cvta_generic_to_shared(&As[s][row][0]) + c16 * 16;
            cp16(ad, xsrc + (size_t)row * (Hh * Ww * Cc) + c16 * 4);
            uint32_t bd = (uint32_t)__cvta_generic_to_shared(&Bs[s][row][0]) + c16 * 16;
            cp16_ef(bd, wsrc + (size_t)row * KDIM + c16 * 4, pol);
        }
    };

    float acc[2][4][4];
#pragma unroll
    for (int mt = 0; mt < 2; mt++)
#pragma unroll
        for (int nt = 0; nt < 4; nt++)
#pragma unroll
            for (int r = 0; r < 4; r++) acc[mt][nt][r] = 0.0f;

    load_chunk(0, 0);
    CP_COMMIT();

    for (int c = 0; c < NCHUNK; c++) {
        const int s = c & 1;
        if (c + 1 < NCHUNK) {
            load_chunk(c + 1, s ^ 1);
            CP_COMMIT();
            asm volatile("cp.async.wait_group 1;" ::: "memory");
        } else {
            asm volatile("cp.async.wait_group 0;" ::: "memory");
        }
        __syncthreads();

#pragma unroll
        for (int k8 = 0; k8 < 4; k8++) {
            const int kb = k8 * 8;
            uint32_t a[2][4], b[4][2];
#pragma unroll
            for (int mt = 0; mt < 2; mt++) {
                const int r0 = warpM + mt * 16 + g;
                a[mt][0] = tf32_bits(As[s][r0][kb + t]);
                a[mt][1] = tf32_bits(As[s][r0 + 8][kb + t]);
                a[mt][2] = tf32_bits(As[s][r0][kb + t + 4]);
                a[mt][3] = tf32_bits(As[s][r0 + 8][kb + t + 4]);
            }
#pragma unroll
            for (int nt = 0; nt < 4; nt++) {
                const int n0 = warpN + nt * 8 + g;
                b[nt][0] = tf32_bits(Bs[s][n0][kb + t]);
                b[nt][1] = tf32_bits(Bs[s][n0][kb + t + 4]);
            }
#pragma unroll
            for (int mt = 0; mt < 2; mt++)
#pragma unroll
                for (int nt = 0; nt < 4; nt++)
                    mma_16n8k8(acc[mt][nt], a[mt], b[nt]);
        }
        __syncthreads();
    }

    // epilogue: D[row=m, col=u] += bias[u]; out[b][oh][ow][u]
#pragma unroll
    for (int mt = 0; mt < 2; mt++) {
        const int r0 = warpM + mt * 16 + g;
#pragma unroll
        for (int nt = 0; nt < 4; nt++) {
            const int col = warpN + nt * 8 + 2 * t;
            const float b0 = bsh[col], b1 = bsh[col + 1];
            float* op0 = out + (((size_t)r0 * OHh + oh) * OWw + ow) * Uu + col;
            float* op1 = out + (((size_t)(r0 + 8) * OHh + oh) * OWw + ow) * Uu + col;
            float2 v0 = make_float2(acc[mt][nt][0] + b0, acc[mt][nt][1] + b1);
            float2 v1 = make_float2(acc[mt][nt][2] + b0, acc[mt][nt][3] + b1);
            *reinterpret_cast<float2*>(op0) = v0;
            *reinterpret_cast<float2*>(op1) = v1;
        }
    }
}

// ---------------- launch ----------------
extern "C" void kernel_launch(void* const* d_in, const int* in_sizes, int n_in,
                              void* d_out, int out_size) {
    (void)in_sizes; (void)n_in; (void)out_size;
    const float* x = (const float*)d_in[0];
    const float* w = (const float*)d_in[1];
    const float* b = (const float*)d_in[2];
    freeconv_mma_kernel<<<OHh * OWw, 128>>>(x, w, b, (float*)d_out);
}